// round 9
// baseline (speedup 1.0000x reference)
#include <cuda_runtime.h>
#include <cuda_fp16.h>
#include <cstdint>

// LightGCN on GB300, round 9: R7 structure restored (meta/dinv, 4-wide
// batches) + pre-scaled layer-1 output so pull2's inner loop is a pure
// unweighted row sum, + zero-row padding (no per-slot weight predication).
// U=100000, I=50000, D=128, E=300000.
#define DIMS 128
#define MAXN 160000
#define ZROW (MAXN - 1)        // never-written, zero-initialized row
#define ADJ_STRIDE 32          // max degree ~22 (Poisson(6) max over 50k)

__device__ int    g_cursor[MAXN];               // degree counter / fill cursor
__device__ float  g_dinv[MAXN];                 // rsqrt(deg), 0 for deg 0
__device__ int    g_adj2[(size_t)MAXN * ADJ_STRIDE];
__device__ __half g_xh[(size_t)MAXN * DIMS];    // fp16 x0   (row ZROW stays 0)
__device__ __half g_y1h[(size_t)MAXN * DIMS];   // fp16 dinv[v]*x1[v] (row ZROW stays 0)

// ---------------------------------------------------------------------------
__global__ void k_zero(int N4) {
    int i = blockIdx.x * blockDim.x + threadIdx.x;
    if (i < N4) reinterpret_cast<int4*>(g_cursor)[i] = make_int4(0, 0, 0, 0);
}

// One endpoint insertion per thread (single atomic chain each).
__global__ void k_fill(const int* __restrict__ src, const int* __restrict__ dst,
                       int E, int U) {
    int t = blockIdx.x * blockDim.x + threadIdx.x;
    if (t >= 2 * E) return;
    int e = (t < E) ? t : t - E;
    int a = __ldg(&src[e]);
    int b = __ldg(&dst[e]) + U;
    int node = (t < E) ? b : a;
    int nbr  = (t < E) ? a : b;
    int p = atomicAdd(&g_cursor[node], 1);
    g_adj2[(size_t)node * ADJ_STRIDE + p] = nbr;
}

__global__ void k_meta(int N) {
    int i = blockIdx.x * blockDim.x + threadIdx.x;
    if (i >= N) return;
    int d = g_cursor[i];
    g_dinv[i] = (d > 0) ? rsqrtf((float)d) : 0.0f;
}

// Convert concat(ue, ie) -> fp16 table; 8 floats per thread.
__global__ void k_convert(const float* __restrict__ ue, const float* __restrict__ ie,
                          int UD, int ND8) {
    int i = blockIdx.x * blockDim.x + threadIdx.x;
    if (i >= ND8) return;
    int base = i * 8;
    const float4* p = (base < UD)
        ? reinterpret_cast<const float4*>(ue + base)
        : reinterpret_cast<const float4*>(ie + (base - UD));
    float4 v0 = __ldg(p);
    float4 v1 = __ldg(p + 1);
    __half2 h0 = __floats2half2_rn(v0.x, v0.y);
    __half2 h1 = __floats2half2_rn(v0.z, v0.w);
    __half2 h2 = __floats2half2_rn(v1.x, v1.y);
    __half2 h3 = __floats2half2_rn(v1.z, v1.w);
    uint4 packed;
    packed.x = *reinterpret_cast<unsigned*>(&h0);
    packed.y = *reinterpret_cast<unsigned*>(&h1);
    packed.z = *reinterpret_cast<unsigned*>(&h2);
    packed.w = *reinterpret_cast<unsigned*>(&h3);
    reinterpret_cast<uint4*>(g_xh)[i] = packed;
}

// ---------------------------------------------------------------------------
struct Acc8 { float f[8]; };

__device__ __forceinline__ void fma8h(Acc8& acc, float w, uint4 r) {
    __half2 h0 = *reinterpret_cast<__half2*>(&r.x);
    __half2 h1 = *reinterpret_cast<__half2*>(&r.y);
    __half2 h2 = *reinterpret_cast<__half2*>(&r.z);
    __half2 h3 = *reinterpret_cast<__half2*>(&r.w);
    float2 f0 = __half22float2(h0), f1 = __half22float2(h1);
    float2 f2 = __half22float2(h2), f3 = __half22float2(h3);
    acc.f[0] = fmaf(w, f0.x, acc.f[0]);  acc.f[1] = fmaf(w, f0.y, acc.f[1]);
    acc.f[2] = fmaf(w, f1.x, acc.f[2]);  acc.f[3] = fmaf(w, f1.y, acc.f[3]);
    acc.f[4] = fmaf(w, f2.x, acc.f[4]);  acc.f[5] = fmaf(w, f2.y, acc.f[5]);
    acc.f[6] = fmaf(w, f3.x, acc.f[6]);  acc.f[7] = fmaf(w, f3.y, acc.f[7]);
}

__device__ __forceinline__ void add8h(Acc8& acc, uint4 r) {
    __half2 h0 = *reinterpret_cast<__half2*>(&r.x);
    __half2 h1 = *reinterpret_cast<__half2*>(&r.y);
    __half2 h2 = *reinterpret_cast<__half2*>(&r.z);
    __half2 h3 = *reinterpret_cast<__half2*>(&r.w);
    float2 f0 = __half22float2(h0), f1 = __half22float2(h1);
    float2 f2 = __half22float2(h2), f3 = __half22float2(h3);
    acc.f[0] += f0.x;  acc.f[1] += f0.y;
    acc.f[2] += f1.x;  acc.f[3] += f1.y;
    acc.f[4] += f2.x;  acc.f[5] += f2.y;
    acc.f[6] += f3.x;  acc.f[7] += f3.y;
}

// Layer 1: y1h[v] = fp16( dinv[v]^2 * sum dinv[u]*xh[u] ).  2 nodes per warp,
// 4-wide batches, weighted gather (dinv table), zero-row padding.
__global__ void k_pull1(int N) {
    int w = (blockIdx.x * blockDim.x + threadIdx.x) >> 5;
    if (w * 2 >= N) return;
    int lane = threadIdx.x & 31;
    int v = min(w * 2 + (lane >> 4), N - 1);
    int sub = lane & 15;

    int n = __ldg(&g_cursor[v]);
    float dv = (n > 0) ? rsqrtf((float)n) : 0.0f;
    int dmax = __reduce_max_sync(0xffffffffu, n);
    const int* arow = &g_adj2[(size_t)v * ADJ_STRIDE];

    Acc8 acc = {};
    for (int j = 0; j < dmax; j += 4) {
        int4 ids = __ldg(reinterpret_cast<const int4*>(arow) + (j >> 2));
        int u0 = (j + 0 < n) ? ids.x : ZROW;
        int u1 = (j + 1 < n) ? ids.y : ZROW;
        int u2 = (j + 2 < n) ? ids.z : ZROW;
        int u3 = (j + 3 < n) ? ids.w : ZROW;
        float w0 = __ldg(&g_dinv[u0]);
        float w1 = __ldg(&g_dinv[u1]);
        float w2 = __ldg(&g_dinv[u2]);
        float w3 = __ldg(&g_dinv[u3]);
        uint4 a0 = __ldg(&reinterpret_cast<const uint4*>(g_xh + (size_t)u0 * DIMS)[sub]);
        uint4 a1 = __ldg(&reinterpret_cast<const uint4*>(g_xh + (size_t)u1 * DIMS)[sub]);
        uint4 a2 = __ldg(&reinterpret_cast<const uint4*>(g_xh + (size_t)u2 * DIMS)[sub]);
        uint4 a3 = __ldg(&reinterpret_cast<const uint4*>(g_xh + (size_t)u3 * DIMS)[sub]);
        fma8h(acc, w0, a0); fma8h(acc, w1, a1);
        fma8h(acc, w2, a2); fma8h(acc, w3, a3);
    }

    float s = dv * dv;   // store y1 = dinv[v] * x1[v] = dv^2 * acc
    __half2 h0 = __floats2half2_rn(acc.f[0] * s, acc.f[1] * s);
    __half2 h1 = __floats2half2_rn(acc.f[2] * s, acc.f[3] * s);
    __half2 h2 = __floats2half2_rn(acc.f[4] * s, acc.f[5] * s);
    __half2 h3 = __floats2half2_rn(acc.f[6] * s, acc.f[7] * s);
    uint4 packed;
    packed.x = *reinterpret_cast<unsigned*>(&h0);
    packed.y = *reinterpret_cast<unsigned*>(&h1);
    packed.z = *reinterpret_cast<unsigned*>(&h2);
    packed.w = *reinterpret_cast<unsigned*>(&h3);
    reinterpret_cast<uint4*>(&g_y1h[(size_t)v * DIMS])[sub] = packed;
}

__device__ __forceinline__ void unpack8(uint4 r, float* f) {
    __half2 h0 = *reinterpret_cast<__half2*>(&r.x);
    __half2 h1 = *reinterpret_cast<__half2*>(&r.y);
    __half2 h2 = *reinterpret_cast<__half2*>(&r.z);
    __half2 h3 = *reinterpret_cast<__half2*>(&r.w);
    float2 a = __half22float2(h0), b = __half22float2(h1);
    float2 c = __half22float2(h2), d = __half22float2(h3);
    f[0] = a.x; f[1] = a.y; f[2] = b.x; f[3] = b.y;
    f[4] = c.x; f[5] = c.y; f[6] = d.x; f[7] = d.y;
}

// Layer 2 + finalize. Inner loop is a PURE SUM of y1 rows (weights already
// folded into y1 by pull1): x2[v] = dinv[v] * sum_u y1[u].
// out[v] = (x0[v] + x1[v] + x2[v]) / 3, with x1[v] = y1[v]*sqrt(deg(v)).
__global__ void k_pull2(float* __restrict__ out, int N) {
    int w = (blockIdx.x * blockDim.x + threadIdx.x) >> 5;
    if (w * 2 >= N) return;
    int lane = threadIdx.x & 31;
    int v = min(w * 2 + (lane >> 4), N - 1);
    int sub = lane & 15;

    int n = __ldg(&g_cursor[v]);
    float dv = (n > 0) ? rsqrtf((float)n) : 0.0f;
    float sq = (n > 0) ? sqrtf((float)n) : 0.0f;
    int dmax = __reduce_max_sync(0xffffffffu, n);
    const int* arow = &g_adj2[(size_t)v * ADJ_STRIDE];

    Acc8 acc = {};
    for (int j = 0; j < dmax; j += 4) {
        int4 ids = __ldg(reinterpret_cast<const int4*>(arow) + (j >> 2));
        int u0 = (j + 0 < n) ? ids.x : ZROW;
        int u1 = (j + 1 < n) ? ids.y : ZROW;
        int u2 = (j + 2 < n) ? ids.z : ZROW;
        int u3 = (j + 3 < n) ? ids.w : ZROW;
        uint4 a0 = __ldg(&reinterpret_cast<const uint4*>(g_y1h + (size_t)u0 * DIMS)[sub]);
        uint4 a1 = __ldg(&reinterpret_cast<const uint4*>(g_y1h + (size_t)u1 * DIMS)[sub]);
        uint4 a2 = __ldg(&reinterpret_cast<const uint4*>(g_y1h + (size_t)u2 * DIMS)[sub]);
        uint4 a3 = __ldg(&reinterpret_cast<const uint4*>(g_y1h + (size_t)u3 * DIMS)[sub]);
        add8h(acc, a0); add8h(acc, a1);
        add8h(acc, a2); add8h(acc, a3);
    }

    uint4 x0r = __ldg(&reinterpret_cast<const uint4*>(g_xh  + (size_t)v * DIMS)[sub]);
    uint4 y1r = __ldg(&reinterpret_cast<const uint4*>(g_y1h + (size_t)v * DIMS)[sub]);
    float x0[8], y1[8];
    unpack8(x0r, x0);
    unpack8(y1r, y1);

    const float third = 1.0f / 3.0f;
    float4 oa, ob;
    oa.x = (x0[0] + y1[0] * sq + dv * acc.f[0]) * third;
    oa.y = (x0[1] + y1[1] * sq + dv * acc.f[1]) * third;
    oa.z = (x0[2] + y1[2] * sq + dv * acc.f[2]) * third;
    oa.w = (x0[3] + y1[3] * sq + dv * acc.f[3]) * third;
    ob.x = (x0[4] + y1[4] * sq + dv * acc.f[4]) * third;
    ob.y = (x0[5] + y1[5] * sq + dv * acc.f[5]) * third;
    ob.z = (x0[6] + y1[6] * sq + dv * acc.f[6]) * third;
    ob.w = (x0[7] + y1[7] * sq + dv * acc.f[7]) * third;
    float4* op = reinterpret_cast<float4*>(&out[(size_t)v * DIMS]);
    op[sub * 2]     = oa;
    op[sub * 2 + 1] = ob;
}

// ---------------------------------------------------------------------------
extern "C" void kernel_launch(void* const* d_in, const int* in_sizes, int n_in,
                              void* d_out, int out_size) {
    const float* user_emb = (const float*)d_in[0];
    const float* item_emb = (const float*)d_in[1];
    const int*   ui_src   = (const int*)d_in[2];
    const int*   ui_dst   = (const int*)d_in[3];
    // d_in[4..5] (iu_src/iu_dst) are the exact transpose; handled implicitly.

    const int U  = in_sizes[0] / DIMS;
    const int I  = in_sizes[1] / DIMS;
    const int E  = in_sizes[2];
    const int N  = U + I;
    const int UD = U * DIMS;
    const int ND8 = (N * DIMS) / 8;
    const int N4 = (N + 3) / 4;

    float* out = (float*)d_out;

    // One-time infra (created on the first, non-captured, correctness call).
    static cudaStream_t s_side = nullptr;
    static cudaEvent_t ev_fork = nullptr, ev_join = nullptr;
    if (s_side == nullptr) {
        cudaStreamCreateWithFlags(&s_side, cudaStreamNonBlocking);
        cudaEventCreateWithFlags(&ev_fork, cudaEventDisableTiming);
        cudaEventCreateWithFlags(&ev_join, cudaEventDisableTiming);
    }

    const int T = 256;
    int blks_n4 = (N4 + T - 1) / T;
    int blks_n  = (N + T - 1) / T;
    int blks_f  = (2 * E + T - 1) / T;
    int blks_c  = (ND8 + T - 1) / T;
    int warps   = (N + 1) / 2;                 // 2 nodes per warp
    int blks_pl = (warps * 32 + T - 1) / T;

    // Fork: convert (DRAM-bound) runs concurrently with the graph build.
    cudaEventRecord(ev_fork, 0);
    cudaStreamWaitEvent(s_side, ev_fork, 0);
    k_convert<<<blks_c, T, 0, s_side>>>(user_emb, item_emb, UD, ND8);
    cudaEventRecord(ev_join, s_side);

    // Build chain on the main stream.
    k_zero<<<blks_n4, T>>>(N4);
    k_fill<<<blks_f, T>>>(ui_src, ui_dst, E, U);
    k_meta<<<blks_n, T>>>(N);

    // Join: pull1 needs both the adjacency/dinv and the fp16 table.
    cudaStreamWaitEvent(0, ev_join, 0);
    k_pull1<<<blks_pl, T>>>(N);
    k_pull2<<<blks_pl, T>>>(out, N);
}

// round 10
// speedup vs baseline: 1.2582x; 1.2582x over previous
#include <cuda_runtime.h>
#include <cuda_fp16.h>
#include <cstdint>

// LightGCN on GB300, round 10: exact R7 structure (known 109.2us) with ONE
// change: pull1 stores dinv[v]*x1[v], so pull2's inner loop is an unweighted
// row sum (no dinv gathers / no FMA weights). ZROW zero-row padding.
// U=100000, I=50000, D=128, E=300000.
#define DIMS 128
#define MAXN 160000
#define ZROW (MAXN - 1)        // never written; stays zero across replays
#define ADJ_STRIDE 64

__device__ int    g_cursor[MAXN];               // degree counter / fill cursor
__device__ int2   g_meta[MAXN];                 // {deg, dinv_bits}
__device__ float  g_dinv[MAXN];                 // rsqrt(deg); dinv[ZROW]=0
__device__ int    g_adj2[(size_t)MAXN * ADJ_STRIDE];
__device__ __half g_xh[(size_t)MAXN * DIMS];    // fp16 x0    (row ZROW = 0)
__device__ __half g_y1h[(size_t)MAXN * DIMS];   // fp16 dinv[v]*x1[v] (row ZROW = 0)

// ---------------------------------------------------------------------------
__global__ void k_zero(int N4) {
    int i = blockIdx.x * blockDim.x + threadIdx.x;
    if (i < N4) reinterpret_cast<int4*>(g_cursor)[i] = make_int4(0, 0, 0, 0);
}

// Edge-per-thread fill (two insertions per thread), H-split — R7 layout.
__device__ __forceinline__ void fill_one(const int* src, const int* dst, int e, int U) {
    int u  = src[e];
    int it = dst[e] + U;
    int p1 = atomicAdd(&g_cursor[it], 1);
    g_adj2[(size_t)it * ADJ_STRIDE + p1] = u;
    int p2 = atomicAdd(&g_cursor[u], 1);
    g_adj2[(size_t)u * ADJ_STRIDE + p2] = it;
}

__global__ void k_fill(const int* __restrict__ src, const int* __restrict__ dst,
                       int E, int U, int H) {
    int t = blockIdx.x * blockDim.x + threadIdx.x;
    if (t >= H) return;
    fill_one(src, dst, t, U);
    int e2 = t + H;
    if (e2 < E) fill_one(src, dst, e2, U);
}

__global__ void k_meta(int N) {
    int i = blockIdx.x * blockDim.x + threadIdx.x;
    if (i >= N) return;
    int d = g_cursor[i];
    float dinv = (d > 0) ? rsqrtf((float)d) : 0.0f;
    g_dinv[i] = dinv;
    g_meta[i] = make_int2(d, __float_as_int(dinv));
}

// Convert concat(ue, ie) -> fp16 table; 8 floats per thread.
__global__ void k_convert(const float* __restrict__ ue, const float* __restrict__ ie,
                          int UD, int ND8) {
    int i = blockIdx.x * blockDim.x + threadIdx.x;
    if (i >= ND8) return;
    int base = i * 8;
    const float4* p = (base < UD)
        ? reinterpret_cast<const float4*>(ue + base)
        : reinterpret_cast<const float4*>(ie + (base - UD));
    float4 v0 = __ldg(p);
    float4 v1 = __ldg(p + 1);
    __half2 h0 = __floats2half2_rn(v0.x, v0.y);
    __half2 h1 = __floats2half2_rn(v0.z, v0.w);
    __half2 h2 = __floats2half2_rn(v1.x, v1.y);
    __half2 h3 = __floats2half2_rn(v1.z, v1.w);
    uint4 packed;
    packed.x = *reinterpret_cast<unsigned*>(&h0);
    packed.y = *reinterpret_cast<unsigned*>(&h1);
    packed.z = *reinterpret_cast<unsigned*>(&h2);
    packed.w = *reinterpret_cast<unsigned*>(&h3);
    reinterpret_cast<uint4*>(g_xh)[i] = packed;
}

// ---------------------------------------------------------------------------
struct Acc8 { float f[8]; };

__device__ __forceinline__ void fma8h(Acc8& acc, float w, uint4 r) {
    __half2 h0 = *reinterpret_cast<__half2*>(&r.x);
    __half2 h1 = *reinterpret_cast<__half2*>(&r.y);
    __half2 h2 = *reinterpret_cast<__half2*>(&r.z);
    __half2 h3 = *reinterpret_cast<__half2*>(&r.w);
    float2 f0 = __half22float2(h0), f1 = __half22float2(h1);
    float2 f2 = __half22float2(h2), f3 = __half22float2(h3);
    acc.f[0] = fmaf(w, f0.x, acc.f[0]);  acc.f[1] = fmaf(w, f0.y, acc.f[1]);
    acc.f[2] = fmaf(w, f1.x, acc.f[2]);  acc.f[3] = fmaf(w, f1.y, acc.f[3]);
    acc.f[4] = fmaf(w, f2.x, acc.f[4]);  acc.f[5] = fmaf(w, f2.y, acc.f[5]);
    acc.f[6] = fmaf(w, f3.x, acc.f[6]);  acc.f[7] = fmaf(w, f3.y, acc.f[7]);
}

__device__ __forceinline__ void add8h(Acc8& acc, uint4 r) {
    __half2 h0 = *reinterpret_cast<__half2*>(&r.x);
    __half2 h1 = *reinterpret_cast<__half2*>(&r.y);
    __half2 h2 = *reinterpret_cast<__half2*>(&r.z);
    __half2 h3 = *reinterpret_cast<__half2*>(&r.w);
    float2 f0 = __half22float2(h0), f1 = __half22float2(h1);
    float2 f2 = __half22float2(h2), f3 = __half22float2(h3);
    acc.f[0] += f0.x;  acc.f[1] += f0.y;
    acc.f[2] += f1.x;  acc.f[3] += f1.y;
    acc.f[4] += f2.x;  acc.f[5] += f2.y;
    acc.f[6] += f3.x;  acc.f[7] += f3.y;
}

// Layer 1: y1h[v] = fp16( dinv[v]^2 * sum dinv[u]*xh[u] ).  2 nodes/warp,
// 4-wide batches; padding via ZROW (dinv[ZROW]=0, xh[ZROW]=0).
__global__ void k_pull1(int N) {
    int w = (blockIdx.x * blockDim.x + threadIdx.x) >> 5;
    if (w * 2 >= N) return;
    int lane = threadIdx.x & 31;
    int v = min(w * 2 + (lane >> 4), N - 1);
    int sub = lane & 15;

    int2 m = __ldg(&g_meta[v]);
    int n = m.x;
    float dv = __int_as_float(m.y);
    int dmax = __reduce_max_sync(0xffffffffu, n);
    const int* arow = &g_adj2[(size_t)v * ADJ_STRIDE];

    Acc8 acc = {};
    for (int j = 0; j < dmax; j += 4) {
        int4 ids = __ldg(reinterpret_cast<const int4*>(arow) + (j >> 2));
        int u0 = (j + 0 < n) ? ids.x : ZROW;
        int u1 = (j + 1 < n) ? ids.y : ZROW;
        int u2 = (j + 2 < n) ? ids.z : ZROW;
        int u3 = (j + 3 < n) ? ids.w : ZROW;
        float w0 = __ldg(&g_dinv[u0]);
        float w1 = __ldg(&g_dinv[u1]);
        float w2 = __ldg(&g_dinv[u2]);
        float w3 = __ldg(&g_dinv[u3]);
        uint4 a0 = __ldg(&reinterpret_cast<const uint4*>(g_xh + (size_t)u0 * DIMS)[sub]);
        uint4 a1 = __ldg(&reinterpret_cast<const uint4*>(g_xh + (size_t)u1 * DIMS)[sub]);
        uint4 a2 = __ldg(&reinterpret_cast<const uint4*>(g_xh + (size_t)u2 * DIMS)[sub]);
        uint4 a3 = __ldg(&reinterpret_cast<const uint4*>(g_xh + (size_t)u3 * DIMS)[sub]);
        fma8h(acc, w0, a0); fma8h(acc, w1, a1);
        fma8h(acc, w2, a2); fma8h(acc, w3, a3);
    }

    float s = dv * dv;   // y1 = dinv[v] * x1[v] = dv^2 * acc
    __half2 h0 = __floats2half2_rn(acc.f[0] * s, acc.f[1] * s);
    __half2 h1 = __floats2half2_rn(acc.f[2] * s, acc.f[3] * s);
    __half2 h2 = __floats2half2_rn(acc.f[4] * s, acc.f[5] * s);
    __half2 h3 = __floats2half2_rn(acc.f[6] * s, acc.f[7] * s);
    uint4 packed;
    packed.x = *reinterpret_cast<unsigned*>(&h0);
    packed.y = *reinterpret_cast<unsigned*>(&h1);
    packed.z = *reinterpret_cast<unsigned*>(&h2);
    packed.w = *reinterpret_cast<unsigned*>(&h3);
    reinterpret_cast<uint4*>(&g_y1h[(size_t)v * DIMS])[sub] = packed;
}

__device__ __forceinline__ void unpack8(uint4 r, float* f) {
    __half2 h0 = *reinterpret_cast<__half2*>(&r.x);
    __half2 h1 = *reinterpret_cast<__half2*>(&r.y);
    __half2 h2 = *reinterpret_cast<__half2*>(&r.z);
    __half2 h3 = *reinterpret_cast<__half2*>(&r.w);
    float2 a = __half22float2(h0), b = __half22float2(h1);
    float2 c = __half22float2(h2), d = __half22float2(h3);
    f[0] = a.x; f[1] = a.y; f[2] = b.x; f[3] = b.y;
    f[4] = c.x; f[5] = c.y; f[6] = d.x; f[7] = d.y;
}

// Layer 2 + finalize. Inner loop: PURE SUM of y1 rows (weights pre-folded):
// x2[v] = dinv[v] * sum_u y1[u];  x1[v] = y1[v]*sqrt(deg(v)).
// out[v] = (x0[v] + x1[v] + x2[v]) / 3.
__global__ void k_pull2(float* __restrict__ out, int N) {
    int w = (blockIdx.x * blockDim.x + threadIdx.x) >> 5;
    if (w * 2 >= N) return;
    int lane = threadIdx.x & 31;
    int v = min(w * 2 + (lane >> 4), N - 1);
    int sub = lane & 15;

    int2 m = __ldg(&g_meta[v]);
    int n = m.x;
    float dv = __int_as_float(m.y);
    float sq = (n > 0) ? sqrtf((float)n) : 0.0f;
    int dmax = __reduce_max_sync(0xffffffffu, n);
    const int* arow = &g_adj2[(size_t)v * ADJ_STRIDE];

    Acc8 acc = {};
    for (int j = 0; j < dmax; j += 4) {
        int4 ids = __ldg(reinterpret_cast<const int4*>(arow) + (j >> 2));
        int u0 = (j + 0 < n) ? ids.x : ZROW;
        int u1 = (j + 1 < n) ? ids.y : ZROW;
        int u2 = (j + 2 < n) ? ids.z : ZROW;
        int u3 = (j + 3 < n) ? ids.w : ZROW;
        uint4 a0 = __ldg(&reinterpret_cast<const uint4*>(g_y1h + (size_t)u0 * DIMS)[sub]);
        uint4 a1 = __ldg(&reinterpret_cast<const uint4*>(g_y1h + (size_t)u1 * DIMS)[sub]);
        uint4 a2 = __ldg(&reinterpret_cast<const uint4*>(g_y1h + (size_t)u2 * DIMS)[sub]);
        uint4 a3 = __ldg(&reinterpret_cast<const uint4*>(g_y1h + (size_t)u3 * DIMS)[sub]);
        add8h(acc, a0); add8h(acc, a1);
        add8h(acc, a2); add8h(acc, a3);
    }

    uint4 x0r = __ldg(&reinterpret_cast<const uint4*>(g_xh  + (size_t)v * DIMS)[sub]);
    uint4 y1r = __ldg(&reinterpret_cast<const uint4*>(g_y1h + (size_t)v * DIMS)[sub]);
    float x0[8], y1[8];
    unpack8(x0r, x0);
    unpack8(y1r, y1);

    const float third = 1.0f / 3.0f;
    float4 oa, ob;
    oa.x = (x0[0] + y1[0] * sq + dv * acc.f[0]) * third;
    oa.y = (x0[1] + y1[1] * sq + dv * acc.f[1]) * third;
    oa.z = (x0[2] + y1[2] * sq + dv * acc.f[2]) * third;
    oa.w = (x0[3] + y1[3] * sq + dv * acc.f[3]) * third;
    ob.x = (x0[4] + y1[4] * sq + dv * acc.f[4]) * third;
    ob.y = (x0[5] + y1[5] * sq + dv * acc.f[5]) * third;
    ob.z = (x0[6] + y1[6] * sq + dv * acc.f[6]) * third;
    ob.w = (x0[7] + y1[7] * sq + dv * acc.f[7]) * third;
    float4* op = reinterpret_cast<float4*>(&out[(size_t)v * DIMS]);
    op[sub * 2]     = oa;
    op[sub * 2 + 1] = ob;
}

// ---------------------------------------------------------------------------
extern "C" void kernel_launch(void* const* d_in, const int* in_sizes, int n_in,
                              void* d_out, int out_size) {
    const float* user_emb = (const float*)d_in[0];
    const float* item_emb = (const float*)d_in[1];
    const int*   ui_src   = (const int*)d_in[2];
    const int*   ui_dst   = (const int*)d_in[3];
    // d_in[4..5] (iu_src/iu_dst) are the exact transpose; handled implicitly.

    const int U  = in_sizes[0] / DIMS;
    const int I  = in_sizes[1] / DIMS;
    const int E  = in_sizes[2];
    const int N  = U + I;
    const int UD = U * DIMS;
    const int ND8 = (N * DIMS) / 8;
    const int N4 = (N + 3) / 4;
    const int H  = (E + 1) / 2;

    float* out = (float*)d_out;

    // One-time infra (created on the first, non-captured, correctness call).
    static cudaStream_t s_side = nullptr;
    static cudaEvent_t ev_fork = nullptr, ev_join = nullptr;
    if (s_side == nullptr) {
        cudaStreamCreateWithFlags(&s_side, cudaStreamNonBlocking);
        cudaEventCreateWithFlags(&ev_fork, cudaEventDisableTiming);
        cudaEventCreateWithFlags(&ev_join, cudaEventDisableTiming);
    }

    const int T = 256;
    int blks_n4 = (N4 + T - 1) / T;
    int blks_n  = (N + T - 1) / T;
    int blks_h  = (H + T - 1) / T;
    int blks_c  = (ND8 + T - 1) / T;
    int warps   = (N + 1) / 2;                 // 2 nodes per warp
    int blks_pl = (warps * 32 + T - 1) / T;

    // Fork: convert (DRAM-bound) runs concurrently with the graph build.
    cudaEventRecord(ev_fork, 0);
    cudaStreamWaitEvent(s_side, ev_fork, 0);
    k_convert<<<blks_c, T, 0, s_side>>>(user_emb, item_emb, UD, ND8);
    cudaEventRecord(ev_join, s_side);

    // Build chain on the main stream.
    k_zero<<<blks_n4, T>>>(N4);
    k_fill<<<blks_h, T>>>(ui_src, ui_dst, E, U, H);
    k_meta<<<blks_n, T>>>(N);

    // Join: pull1 needs both the adjacency/dinv and the fp16 table.
    cudaStreamWaitEvent(0, ev_join, 0);
    k_pull1<<<blks_pl, T>>>(N);
    k_pull2<<<blks_pl, T>>>(out, N);
}

// round 11
// speedup vs baseline: 1.2843x; 1.0208x over previous
#include <cuda_runtime.h>
#include <cuda_fp16.h>
#include <cstdint>

// LightGCN on GB300, round 11: R10 structure with fp16 (HFMA2/HADD2)
// neighbor accumulation — cuts the pull inner-loop instruction count ~2.5x
// (was 8 cvt + 8 FFMA per uint4; now 4 packed-half ops). Epilogues fp32.
// U=100000, I=50000, D=128, E=300000.
#define DIMS 128
#define MAXN 160000
#define ZROW (MAXN - 1)        // never written; stays zero across replays
#define ADJ_STRIDE 64

__device__ int    g_cursor[MAXN];               // degree counter / fill cursor
__device__ int2   g_meta[MAXN];                 // {deg, dinv_bits(fp32)}
__device__ float  g_dinv[MAXN];                 // rsqrt(deg) fp32; [ZROW]=0
__device__ __half g_dinvh[MAXN];                // rsqrt(deg) fp16; [ZROW]=0
__device__ int    g_adj2[(size_t)MAXN * ADJ_STRIDE];
__device__ __half g_xh[(size_t)MAXN * DIMS];    // fp16 x0    (row ZROW = 0)
__device__ __half g_y1h[(size_t)MAXN * DIMS];   // fp16 dinv[v]*x1[v] (ZROW = 0)

// ---------------------------------------------------------------------------
__global__ void k_zero(int N4) {
    int i = blockIdx.x * blockDim.x + threadIdx.x;
    if (i < N4) reinterpret_cast<int4*>(g_cursor)[i] = make_int4(0, 0, 0, 0);
}

// Edge-per-thread fill (two insertions per thread), H-split — R7/R10 layout.
__device__ __forceinline__ void fill_one(const int* src, const int* dst, int e, int U) {
    int u  = src[e];
    int it = dst[e] + U;
    int p1 = atomicAdd(&g_cursor[it], 1);
    g_adj2[(size_t)it * ADJ_STRIDE + p1] = u;
    int p2 = atomicAdd(&g_cursor[u], 1);
    g_adj2[(size_t)u * ADJ_STRIDE + p2] = it;
}

__global__ void k_fill(const int* __restrict__ src, const int* __restrict__ dst,
                       int E, int U, int H) {
    int t = blockIdx.x * blockDim.x + threadIdx.x;
    if (t >= H) return;
    fill_one(src, dst, t, U);
    int e2 = t + H;
    if (e2 < E) fill_one(src, dst, e2, U);
}

__global__ void k_meta(int N) {
    int i = blockIdx.x * blockDim.x + threadIdx.x;
    if (i >= N) return;
    int d = g_cursor[i];
    float dinv = (d > 0) ? rsqrtf((float)d) : 0.0f;
    g_dinv[i]  = dinv;
    g_dinvh[i] = __float2half_rn(dinv);
    g_meta[i]  = make_int2(d, __float_as_int(dinv));
}

// Convert concat(ue, ie) -> fp16 table; 8 floats per thread.
__global__ void k_convert(const float* __restrict__ ue, const float* __restrict__ ie,
                          int UD, int ND8) {
    int i = blockIdx.x * blockDim.x + threadIdx.x;
    if (i >= ND8) return;
    int base = i * 8;
    const float4* p = (base < UD)
        ? reinterpret_cast<const float4*>(ue + base)
        : reinterpret_cast<const float4*>(ie + (base - UD));
    float4 v0 = __ldg(p);
    float4 v1 = __ldg(p + 1);
    __half2 h0 = __floats2half2_rn(v0.x, v0.y);
    __half2 h1 = __floats2half2_rn(v0.z, v0.w);
    __half2 h2 = __floats2half2_rn(v1.x, v1.y);
    __half2 h3 = __floats2half2_rn(v1.z, v1.w);
    uint4 packed;
    packed.x = *reinterpret_cast<unsigned*>(&h0);
    packed.y = *reinterpret_cast<unsigned*>(&h1);
    packed.z = *reinterpret_cast<unsigned*>(&h2);
    packed.w = *reinterpret_cast<unsigned*>(&h3);
    reinterpret_cast<uint4*>(g_xh)[i] = packed;
}

// ---------------------------------------------------------------------------
struct AccH { __half2 h[4]; };   // 8 halves

__device__ __forceinline__ void hfma4(AccH& acc, __half2 w2, uint4 r) {
    acc.h[0] = __hfma2(w2, *reinterpret_cast<__half2*>(&r.x), acc.h[0]);
    acc.h[1] = __hfma2(w2, *reinterpret_cast<__half2*>(&r.y), acc.h[1]);
    acc.h[2] = __hfma2(w2, *reinterpret_cast<__half2*>(&r.z), acc.h[2]);
    acc.h[3] = __hfma2(w2, *reinterpret_cast<__half2*>(&r.w), acc.h[3]);
}

__device__ __forceinline__ void hadd4(AccH& acc, uint4 r) {
    acc.h[0] = __hadd2(acc.h[0], *reinterpret_cast<__half2*>(&r.x));
    acc.h[1] = __hadd2(acc.h[1], *reinterpret_cast<__half2*>(&r.y));
    acc.h[2] = __hadd2(acc.h[2], *reinterpret_cast<__half2*>(&r.z));
    acc.h[3] = __hadd2(acc.h[3], *reinterpret_cast<__half2*>(&r.w));
}

__device__ __forceinline__ void acc_to_f(const AccH& acc, float* f) {
    float2 a = __half22float2(acc.h[0]);
    float2 b = __half22float2(acc.h[1]);
    float2 c = __half22float2(acc.h[2]);
    float2 d = __half22float2(acc.h[3]);
    f[0] = a.x; f[1] = a.y; f[2] = b.x; f[3] = b.y;
    f[4] = c.x; f[5] = c.y; f[6] = d.x; f[7] = d.y;
}

// Layer 1: y1h[v] = fp16( dinv[v]^2 * sum dinv[u]*xh[u] ).  2 nodes/warp,
// 4-wide batches, fp16 HFMA2 accumulation, ZROW padding.
__global__ void k_pull1(int N) {
    int w = (blockIdx.x * blockDim.x + threadIdx.x) >> 5;
    if (w * 2 >= N) return;
    int lane = threadIdx.x & 31;
    int v = min(w * 2 + (lane >> 4), N - 1);
    int sub = lane & 15;

    int2 m = __ldg(&g_meta[v]);
    int n = m.x;
    float dv = __int_as_float(m.y);
    int dmax = __reduce_max_sync(0xffffffffu, n);
    const int* arow = &g_adj2[(size_t)v * ADJ_STRIDE];

    AccH acc = {};
    for (int j = 0; j < dmax; j += 4) {
        int4 ids = __ldg(reinterpret_cast<const int4*>(arow) + (j >> 2));
        int u0 = (j + 0 < n) ? ids.x : ZROW;
        int u1 = (j + 1 < n) ? ids.y : ZROW;
        int u2 = (j + 2 < n) ? ids.z : ZROW;
        int u3 = (j + 3 < n) ? ids.w : ZROW;
        __half w0 = __ldg(&g_dinvh[u0]);
        __half w1 = __ldg(&g_dinvh[u1]);
        __half w2 = __ldg(&g_dinvh[u2]);
        __half w3 = __ldg(&g_dinvh[u3]);
        uint4 a0 = __ldg(&reinterpret_cast<const uint4*>(g_xh + (size_t)u0 * DIMS)[sub]);
        uint4 a1 = __ldg(&reinterpret_cast<const uint4*>(g_xh + (size_t)u1 * DIMS)[sub]);
        uint4 a2 = __ldg(&reinterpret_cast<const uint4*>(g_xh + (size_t)u2 * DIMS)[sub]);
        uint4 a3 = __ldg(&reinterpret_cast<const uint4*>(g_xh + (size_t)u3 * DIMS)[sub]);
        hfma4(acc, __half2half2(w0), a0);
        hfma4(acc, __half2half2(w1), a1);
        hfma4(acc, __half2half2(w2), a2);
        hfma4(acc, __half2half2(w3), a3);
    }

    float f[8];
    acc_to_f(acc, f);
    float s = dv * dv;   // y1 = dinv[v] * x1[v] = dv^2 * acc
    __half2 h0 = __floats2half2_rn(f[0] * s, f[1] * s);
    __half2 h1 = __floats2half2_rn(f[2] * s, f[3] * s);
    __half2 h2 = __floats2half2_rn(f[4] * s, f[5] * s);
    __half2 h3 = __floats2half2_rn(f[6] * s, f[7] * s);
    uint4 packed;
    packed.x = *reinterpret_cast<unsigned*>(&h0);
    packed.y = *reinterpret_cast<unsigned*>(&h1);
    packed.z = *reinterpret_cast<unsigned*>(&h2);
    packed.w = *reinterpret_cast<unsigned*>(&h3);
    reinterpret_cast<uint4*>(&g_y1h[(size_t)v * DIMS])[sub] = packed;
}

__device__ __forceinline__ void unpack8(uint4 r, float* f) {
    float2 a = __half22float2(*reinterpret_cast<__half2*>(&r.x));
    float2 b = __half22float2(*reinterpret_cast<__half2*>(&r.y));
    float2 c = __half22float2(*reinterpret_cast<__half2*>(&r.z));
    float2 d = __half22float2(*reinterpret_cast<__half2*>(&r.w));
    f[0] = a.x; f[1] = a.y; f[2] = b.x; f[3] = b.y;
    f[4] = c.x; f[5] = c.y; f[6] = d.x; f[7] = d.y;
}

// Layer 2 + finalize. Inner loop: pure HADD2 sum of y1 rows.
// x2[v] = dinv[v] * sum_u y1[u];  x1[v] = y1[v]*sqrt(deg(v)).
// out[v] = (x0[v] + x1[v] + x2[v]) / 3.
__global__ void k_pull2(float* __restrict__ out, int N) {
    int w = (blockIdx.x * blockDim.x + threadIdx.x) >> 5;
    if (w * 2 >= N) return;
    int lane = threadIdx.x & 31;
    int v = min(w * 2 + (lane >> 4), N - 1);
    int sub = lane & 15;

    int2 m = __ldg(&g_meta[v]);
    int n = m.x;
    float dv = __int_as_float(m.y);
    float sq = (n > 0) ? sqrtf((float)n) : 0.0f;
    int dmax = __reduce_max_sync(0xffffffffu, n);
    const int* arow = &g_adj2[(size_t)v * ADJ_STRIDE];

    AccH acc = {};
    for (int j = 0; j < dmax; j += 4) {
        int4 ids = __ldg(reinterpret_cast<const int4*>(arow) + (j >> 2));
        int u0 = (j + 0 < n) ? ids.x : ZROW;
        int u1 = (j + 1 < n) ? ids.y : ZROW;
        int u2 = (j + 2 < n) ? ids.z : ZROW;
        int u3 = (j + 3 < n) ? ids.w : ZROW;
        uint4 a0 = __ldg(&reinterpret_cast<const uint4*>(g_y1h + (size_t)u0 * DIMS)[sub]);
        uint4 a1 = __ldg(&reinterpret_cast<const uint4*>(g_y1h + (size_t)u1 * DIMS)[sub]);
        uint4 a2 = __ldg(&reinterpret_cast<const uint4*>(g_y1h + (size_t)u2 * DIMS)[sub]);
        uint4 a3 = __ldg(&reinterpret_cast<const uint4*>(g_y1h + (size_t)u3 * DIMS)[sub]);
        hadd4(acc, a0); hadd4(acc, a1);
        hadd4(acc, a2); hadd4(acc, a3);
    }

    float af[8];
    acc_to_f(acc, af);

    uint4 x0r = __ldg(&reinterpret_cast<const uint4*>(g_xh  + (size_t)v * DIMS)[sub]);
    uint4 y1r = __ldg(&reinterpret_cast<const uint4*>(g_y1h + (size_t)v * DIMS)[sub]);
    float x0[8], y1[8];
    unpack8(x0r, x0);
    unpack8(y1r, y1);

    const float third = 1.0f / 3.0f;
    float4 oa, ob;
    oa.x = (x0[0] + y1[0] * sq + dv * af[0]) * third;
    oa.y = (x0[1] + y1[1] * sq + dv * af[1]) * third;
    oa.z = (x0[2] + y1[2] * sq + dv * af[2]) * third;
    oa.w = (x0[3] + y1[3] * sq + dv * af[3]) * third;
    ob.x = (x0[4] + y1[4] * sq + dv * af[4]) * third;
    ob.y = (x0[5] + y1[5] * sq + dv * af[5]) * third;
    ob.z = (x0[6] + y1[6] * sq + dv * af[6]) * third;
    ob.w = (x0[7] + y1[7] * sq + dv * af[7]) * third;
    float4* op = reinterpret_cast<float4*>(&out[(size_t)v * DIMS]);
    op[sub * 2]     = oa;
    op[sub * 2 + 1] = ob;
}

// ---------------------------------------------------------------------------
extern "C" void kernel_launch(void* const* d_in, const int* in_sizes, int n_in,
                              void* d_out, int out_size) {
    const float* user_emb = (const float*)d_in[0];
    const float* item_emb = (const float*)d_in[1];
    const int*   ui_src   = (const int*)d_in[2];
    const int*   ui_dst   = (const int*)d_in[3];
    // d_in[4..5] (iu_src/iu_dst) are the exact transpose; handled implicitly.

    const int U  = in_sizes[0] / DIMS;
    const int I  = in_sizes[1] / DIMS;
    const int E  = in_sizes[2];
    const int N  = U + I;
    const int UD = U * DIMS;
    const int ND8 = (N * DIMS) / 8;
    const int N4 = (N + 3) / 4;
    const int H  = (E + 1) / 2;

    float* out = (float*)d_out;

    // One-time infra (created on the first, non-captured, correctness call).
    static cudaStream_t s_side = nullptr;
    static cudaEvent_t ev_fork = nullptr, ev_join = nullptr;
    if (s_side == nullptr) {
        cudaStreamCreateWithFlags(&s_side, cudaStreamNonBlocking);
        cudaEventCreateWithFlags(&ev_fork, cudaEventDisableTiming);
        cudaEventCreateWithFlags(&ev_join, cudaEventDisableTiming);
    }

    const int T = 256;
    int blks_n4 = (N4 + T - 1) / T;
    int blks_n  = (N + T - 1) / T;
    int blks_h  = (H + T - 1) / T;
    int blks_c  = (ND8 + T - 1) / T;
    int warps   = (N + 1) / 2;                 // 2 nodes per warp
    int blks_pl = (warps * 32 + T - 1) / T;

    // Fork: convert (DRAM-bound) runs concurrently with the graph build.
    cudaEventRecord(ev_fork, 0);
    cudaStreamWaitEvent(s_side, ev_fork, 0);
    k_convert<<<blks_c, T, 0, s_side>>>(user_emb, item_emb, UD, ND8);
    cudaEventRecord(ev_join, s_side);

    // Build chain on the main stream.
    k_zero<<<blks_n4, T>>>(N4);
    k_fill<<<blks_h, T>>>(ui_src, ui_dst, E, U, H);
    k_meta<<<blks_n, T>>>(N);

    // Join: pull1 needs adjacency/dinv tables and the fp16 feature table.
    cudaStreamWaitEvent(0, ev_join, 0);
    k_pull1<<<blks_pl, T>>>(N);
    k_pull2<<<blks_pl, T>>>(out, N);
}

// round 12
// speedup vs baseline: 1.2960x; 1.0091x over previous
#include <cuda_runtime.h>
#include <cuda_fp16.h>
#include <cstdint>

// LightGCN on GB300, round 12: R11 + occupancy push on the pulls
// (__launch_bounds__(256,6) -> 48 warps/SM vs 32) and dead fp32 dinv table
// removed. U=100000, I=50000, D=128, E=300000.
#define DIMS 128
#define MAXN 160000
#define ZROW (MAXN - 1)        // never written; stays zero across replays
#define ADJ_STRIDE 64

__device__ int    g_cursor[MAXN];               // degree counter / fill cursor
__device__ int2   g_meta[MAXN];                 // {deg, dinv_bits(fp32)}
__device__ __half g_dinvh[MAXN];                // rsqrt(deg) fp16; [ZROW]=0
__device__ int    g_adj2[(size_t)MAXN * ADJ_STRIDE];
__device__ __half g_xh[(size_t)MAXN * DIMS];    // fp16 x0    (row ZROW = 0)
__device__ __half g_y1h[(size_t)MAXN * DIMS];   // fp16 dinv[v]*x1[v] (ZROW = 0)

// ---------------------------------------------------------------------------
__global__ void k_zero(int N4) {
    int i = blockIdx.x * blockDim.x + threadIdx.x;
    if (i < N4) reinterpret_cast<int4*>(g_cursor)[i] = make_int4(0, 0, 0, 0);
}

// Edge-per-thread fill (two insertions per thread), H-split.
__device__ __forceinline__ void fill_one(const int* src, const int* dst, int e, int U) {
    int u  = src[e];
    int it = dst[e] + U;
    int p1 = atomicAdd(&g_cursor[it], 1);
    g_adj2[(size_t)it * ADJ_STRIDE + p1] = u;
    int p2 = atomicAdd(&g_cursor[u], 1);
    g_adj2[(size_t)u * ADJ_STRIDE + p2] = it;
}

__global__ void k_fill(const int* __restrict__ src, const int* __restrict__ dst,
                       int E, int U, int H) {
    int t = blockIdx.x * blockDim.x + threadIdx.x;
    if (t >= H) return;
    fill_one(src, dst, t, U);
    int e2 = t + H;
    if (e2 < E) fill_one(src, dst, e2, U);
}

__global__ void k_meta(int N) {
    int i = blockIdx.x * blockDim.x + threadIdx.x;
    if (i >= N) return;
    int d = g_cursor[i];
    float dinv = (d > 0) ? rsqrtf((float)d) : 0.0f;
    g_dinvh[i] = __float2half_rn(dinv);
    g_meta[i]  = make_int2(d, __float_as_int(dinv));
}

// Convert concat(ue, ie) -> fp16 table; 8 floats per thread.
__global__ void k_convert(const float* __restrict__ ue, const float* __restrict__ ie,
                          int UD, int ND8) {
    int i = blockIdx.x * blockDim.x + threadIdx.x;
    if (i >= ND8) return;
    int base = i * 8;
    const float4* p = (base < UD)
        ? reinterpret_cast<const float4*>(ue + base)
        : reinterpret_cast<const float4*>(ie + (base - UD));
    float4 v0 = __ldg(p);
    float4 v1 = __ldg(p + 1);
    __half2 h0 = __floats2half2_rn(v0.x, v0.y);
    __half2 h1 = __floats2half2_rn(v0.z, v0.w);
    __half2 h2 = __floats2half2_rn(v1.x, v1.y);
    __half2 h3 = __floats2half2_rn(v1.z, v1.w);
    uint4 packed;
    packed.x = *reinterpret_cast<unsigned*>(&h0);
    packed.y = *reinterpret_cast<unsigned*>(&h1);
    packed.z = *reinterpret_cast<unsigned*>(&h2);
    packed.w = *reinterpret_cast<unsigned*>(&h3);
    reinterpret_cast<uint4*>(g_xh)[i] = packed;
}

// ---------------------------------------------------------------------------
struct AccH { __half2 h[4]; };   // 8 halves

__device__ __forceinline__ void hfma4(AccH& acc, __half2 w2, uint4 r) {
    acc.h[0] = __hfma2(w2, *reinterpret_cast<__half2*>(&r.x), acc.h[0]);
    acc.h[1] = __hfma2(w2, *reinterpret_cast<__half2*>(&r.y), acc.h[1]);
    acc.h[2] = __hfma2(w2, *reinterpret_cast<__half2*>(&r.z), acc.h[2]);
    acc.h[3] = __hfma2(w2, *reinterpret_cast<__half2*>(&r.w), acc.h[3]);
}

__device__ __forceinline__ void hadd4(AccH& acc, uint4 r) {
    acc.h[0] = __hadd2(acc.h[0], *reinterpret_cast<__half2*>(&r.x));
    acc.h[1] = __hadd2(acc.h[1], *reinterpret_cast<__half2*>(&r.y));
    acc.h[2] = __hadd2(acc.h[2], *reinterpret_cast<__half2*>(&r.z));
    acc.h[3] = __hadd2(acc.h[3], *reinterpret_cast<__half2*>(&r.w));
}

__device__ __forceinline__ void acc_to_f(const AccH& acc, float* f) {
    float2 a = __half22float2(acc.h[0]);
    float2 b = __half22float2(acc.h[1]);
    float2 c = __half22float2(acc.h[2]);
    float2 d = __half22float2(acc.h[3]);
    f[0] = a.x; f[1] = a.y; f[2] = b.x; f[3] = b.y;
    f[4] = c.x; f[5] = c.y; f[6] = d.x; f[7] = d.y;
}

// Layer 1: y1h[v] = fp16( dinv[v]^2 * sum dinv[u]*xh[u] ).  2 nodes/warp,
// 4-wide batches, fp16 HFMA2 accumulation, ZROW padding.
__global__ void __launch_bounds__(256, 6) k_pull1(int N) {
    int w = (blockIdx.x * blockDim.x + threadIdx.x) >> 5;
    if (w * 2 >= N) return;
    int lane = threadIdx.x & 31;
    int v = min(w * 2 + (lane >> 4), N - 1);
    int sub = lane & 15;

    int2 m = __ldg(&g_meta[v]);
    int n = m.x;
    float dv = __int_as_float(m.y);
    int dmax = __reduce_max_sync(0xffffffffu, n);
    const int* arow = &g_adj2[(size_t)v * ADJ_STRIDE];

    AccH acc = {};
    for (int j = 0; j < dmax; j += 4) {
        int4 ids = __ldg(reinterpret_cast<const int4*>(arow) + (j >> 2));
        int u0 = (j + 0 < n) ? ids.x : ZROW;
        int u1 = (j + 1 < n) ? ids.y : ZROW;
        int u2 = (j + 2 < n) ? ids.z : ZROW;
        int u3 = (j + 3 < n) ? ids.w : ZROW;
        __half w0 = __ldg(&g_dinvh[u0]);
        __half w1 = __ldg(&g_dinvh[u1]);
        __half w2 = __ldg(&g_dinvh[u2]);
        __half w3 = __ldg(&g_dinvh[u3]);
        uint4 a0 = __ldg(&reinterpret_cast<const uint4*>(g_xh + (size_t)u0 * DIMS)[sub]);
        uint4 a1 = __ldg(&reinterpret_cast<const uint4*>(g_xh + (size_t)u1 * DIMS)[sub]);
        uint4 a2 = __ldg(&reinterpret_cast<const uint4*>(g_xh + (size_t)u2 * DIMS)[sub]);
        uint4 a3 = __ldg(&reinterpret_cast<const uint4*>(g_xh + (size_t)u3 * DIMS)[sub]);
        hfma4(acc, __half2half2(w0), a0);
        hfma4(acc, __half2half2(w1), a1);
        hfma4(acc, __half2half2(w2), a2);
        hfma4(acc, __half2half2(w3), a3);
    }

    float f[8];
    acc_to_f(acc, f);
    float s = dv * dv;   // y1 = dinv[v] * x1[v] = dv^2 * acc
    __half2 h0 = __floats2half2_rn(f[0] * s, f[1] * s);
    __half2 h1 = __floats2half2_rn(f[2] * s, f[3] * s);
    __half2 h2 = __floats2half2_rn(f[4] * s, f[5] * s);
    __half2 h3 = __floats2half2_rn(f[6] * s, f[7] * s);
    uint4 packed;
    packed.x = *reinterpret_cast<unsigned*>(&h0);
    packed.y = *reinterpret_cast<unsigned*>(&h1);
    packed.z = *reinterpret_cast<unsigned*>(&h2);
    packed.w = *reinterpret_cast<unsigned*>(&h3);
    reinterpret_cast<uint4*>(&g_y1h[(size_t)v * DIMS])[sub] = packed;
}

__device__ __forceinline__ void unpack8(uint4 r, float* f) {
    float2 a = __half22float2(*reinterpret_cast<__half2*>(&r.x));
    float2 b = __half22float2(*reinterpret_cast<__half2*>(&r.y));
    float2 c = __half22float2(*reinterpret_cast<__half2*>(&r.z));
    float2 d = __half22float2(*reinterpret_cast<__half2*>(&r.w));
    f[0] = a.x; f[1] = a.y; f[2] = b.x; f[3] = b.y;
    f[4] = c.x; f[5] = c.y; f[6] = d.x; f[7] = d.y;
}

// Layer 2 + finalize. Inner loop: pure HADD2 sum of y1 rows.
// x2[v] = dinv[v] * sum_u y1[u];  x1[v] = y1[v]*sqrt(deg(v)).
// out[v] = (x0[v] + x1[v] + x2[v]) / 3.
__global__ void __launch_bounds__(256, 6) k_pull2(float* __restrict__ out, int N) {
    int w = (blockIdx.x * blockDim.x + threadIdx.x) >> 5;
    if (w * 2 >= N) return;
    int lane = threadIdx.x & 31;
    int v = min(w * 2 + (lane >> 4), N - 1);
    int sub = lane & 15;

    int2 m = __ldg(&g_meta[v]);
    int n = m.x;
    float dv = __int_as_float(m.y);
    float sq = (n > 0) ? sqrtf((float)n) : 0.0f;
    int dmax = __reduce_max_sync(0xffffffffu, n);
    const int* arow = &g_adj2[(size_t)v * ADJ_STRIDE];

    AccH acc = {};
    for (int j = 0; j < dmax; j += 4) {
        int4 ids = __ldg(reinterpret_cast<const int4*>(arow) + (j >> 2));
        int u0 = (j + 0 < n) ? ids.x : ZROW;
        int u1 = (j + 1 < n) ? ids.y : ZROW;
        int u2 = (j + 2 < n) ? ids.z : ZROW;
        int u3 = (j + 3 < n) ? ids.w : ZROW;
        uint4 a0 = __ldg(&reinterpret_cast<const uint4*>(g_y1h + (size_t)u0 * DIMS)[sub]);
        uint4 a1 = __ldg(&reinterpret_cast<const uint4*>(g_y1h + (size_t)u1 * DIMS)[sub]);
        uint4 a2 = __ldg(&reinterpret_cast<const uint4*>(g_y1h + (size_t)u2 * DIMS)[sub]);
        uint4 a3 = __ldg(&reinterpret_cast<const uint4*>(g_y1h + (size_t)u3 * DIMS)[sub]);
        hadd4(acc, a0); hadd4(acc, a1);
        hadd4(acc, a2); hadd4(acc, a3);
    }

    float af[8];
    acc_to_f(acc, af);

    uint4 x0r = __ldg(&reinterpret_cast<const uint4*>(g_xh  + (size_t)v * DIMS)[sub]);
    uint4 y1r = __ldg(&reinterpret_cast<const uint4*>(g_y1h + (size_t)v * DIMS)[sub]);
    float x0[8], y1[8];
    unpack8(x0r, x0);
    unpack8(y1r, y1);

    const float third = 1.0f / 3.0f;
    float4 oa, ob;
    oa.x = (x0[0] + y1[0] * sq + dv * af[0]) * third;
    oa.y = (x0[1] + y1[1] * sq + dv * af[1]) * third;
    oa.z = (x0[2] + y1[2] * sq + dv * af[2]) * third;
    oa.w = (x0[3] + y1[3] * sq + dv * af[3]) * third;
    ob.x = (x0[4] + y1[4] * sq + dv * af[4]) * third;
    ob.y = (x0[5] + y1[5] * sq + dv * af[5]) * third;
    ob.z = (x0[6] + y1[6] * sq + dv * af[6]) * third;
    ob.w = (x0[7] + y1[7] * sq + dv * af[7]) * third;
    float4* op = reinterpret_cast<float4*>(&out[(size_t)v * DIMS]);
    op[sub * 2]     = oa;
    op[sub * 2 + 1] = ob;
}

// ---------------------------------------------------------------------------
extern "C" void kernel_launch(void* const* d_in, const int* in_sizes, int n_in,
                              void* d_out, int out_size) {
    const float* user_emb = (const float*)d_in[0];
    const float* item_emb = (const float*)d_in[1];
    const int*   ui_src   = (const int*)d_in[2];
    const int*   ui_dst   = (const int*)d_in[3];
    // d_in[4..5] (iu_src/iu_dst) are the exact transpose; handled implicitly.

    const int U  = in_sizes[0] / DIMS;
    const int I  = in_sizes[1] / DIMS;
    const int E  = in_sizes[2];
    const int N  = U + I;
    const int UD = U * DIMS;
    const int ND8 = (N * DIMS) / 8;
    const int N4 = (N + 3) / 4;
    const int H  = (E + 1) / 2;

    float* out = (float*)d_out;

    // One-time infra (created on the first, non-captured, correctness call).
    static cudaStream_t s_side = nullptr;
    static cudaEvent_t ev_fork = nullptr, ev_join = nullptr;
    if (s_side == nullptr) {
        cudaStreamCreateWithFlags(&s_side, cudaStreamNonBlocking);
        cudaEventCreateWithFlags(&ev_fork, cudaEventDisableTiming);
        cudaEventCreateWithFlags(&ev_join, cudaEventDisableTiming);
    }

    const int T = 256;
    int blks_n4 = (N4 + T - 1) / T;
    int blks_n  = (N + T - 1) / T;
    int blks_h  = (H + T - 1) / T;
    int blks_c  = (ND8 + T - 1) / T;
    int warps   = (N + 1) / 2;                 // 2 nodes per warp
    int blks_pl = (warps * 32 + T - 1) / T;

    // Fork: convert (DRAM-bound) runs concurrently with the graph build.
    cudaEventRecord(ev_fork, 0);
    cudaStreamWaitEvent(s_side, ev_fork, 0);
    k_convert<<<blks_c, T, 0, s_side>>>(user_emb, item_emb, UD, ND8);
    cudaEventRecord(ev_join, s_side);

    // Build chain on the main stream.
    k_zero<<<blks_n4, T>>>(N4);
    k_fill<<<blks_h, T>>>(ui_src, ui_dst, E, U, H);
    k_meta<<<blks_n, T>>>(N);

    // Join: pull1 needs adjacency/dinvh tables and the fp16 feature table.
    cudaStreamWaitEvent(0, ev_join, 0);
    k_pull1<<<blks_pl, T>>>(N);
    k_pull2<<<blks_pl, T>>>(out, N);
}

// round 13
// speedup vs baseline: 1.3221x; 1.0201x over previous
#include <cuda_runtime.h>
#include <cuda_fp16.h>
#include <cstdint>

// LightGCN on GB300, round 13: R12 + endpoint-per-thread fill (1 atomic chain
// per thread), fp16 HMUL2 pull1 epilogue, g_meta removed (deg read from
// cursor, rsqrt per node), pull2 self-row prefetch.
// U=100000, I=50000, D=128, E=300000.
#define DIMS 128
#define MAXN 160000
#define ZROW (MAXN - 1)        // never written; stays zero across replays
#define ADJ_STRIDE 64

__device__ int    g_cursor[MAXN];               // degree counter / fill cursor
__device__ __half g_dinvh[MAXN];                // rsqrt(deg) fp16; [ZROW]=0
__device__ int    g_adj2[(size_t)MAXN * ADJ_STRIDE];
__device__ __half g_xh[(size_t)MAXN * DIMS];    // fp16 x0    (row ZROW = 0)
__device__ __half g_y1h[(size_t)MAXN * DIMS];   // fp16 dinv[v]*x1[v] (ZROW = 0)

// ---------------------------------------------------------------------------
__global__ void k_zero(int N4) {
    int i = blockIdx.x * blockDim.x + threadIdx.x;
    if (i < N4) reinterpret_cast<int4*>(g_cursor)[i] = make_int4(0, 0, 0, 0);
}

// One endpoint insertion per thread: t < E -> item-side list, t >= E -> user.
// Exactly one atomic->store chain per thread.
__global__ void k_fill(const int* __restrict__ src, const int* __restrict__ dst,
                       int E, int U) {
    int t = blockIdx.x * blockDim.x + threadIdx.x;
    if (t >= 2 * E) return;
    int e = (t < E) ? t : t - E;
    int a = __ldg(&src[e]);
    int b = __ldg(&dst[e]) + U;
    int node = (t < E) ? b : a;
    int nbr  = (t < E) ? a : b;
    int p = atomicAdd(&g_cursor[node], 1);
    g_adj2[(size_t)node * ADJ_STRIDE + p] = nbr;
}

// dinvh table only (deg stays in g_cursor; pulls rsqrt their own node).
__global__ void k_meta(int N) {
    int i = blockIdx.x * blockDim.x + threadIdx.x;
    if (i >= N) return;
    int d = g_cursor[i];
    float dinv = (d > 0) ? rsqrtf((float)d) : 0.0f;
    g_dinvh[i] = __float2half_rn(dinv);
}

// Convert concat(ue, ie) -> fp16 table; 8 floats per thread.
__global__ void k_convert(const float* __restrict__ ue, const float* __restrict__ ie,
                          int UD, int ND8) {
    int i = blockIdx.x * blockDim.x + threadIdx.x;
    if (i >= ND8) return;
    int base = i * 8;
    const float4* p = (base < UD)
        ? reinterpret_cast<const float4*>(ue + base)
        : reinterpret_cast<const float4*>(ie + (base - UD));
    float4 v0 = __ldg(p);
    float4 v1 = __ldg(p + 1);
    __half2 h0 = __floats2half2_rn(v0.x, v0.y);
    __half2 h1 = __floats2half2_rn(v0.z, v0.w);
    __half2 h2 = __floats2half2_rn(v1.x, v1.y);
    __half2 h3 = __floats2half2_rn(v1.z, v1.w);
    uint4 packed;
    packed.x = *reinterpret_cast<unsigned*>(&h0);
    packed.y = *reinterpret_cast<unsigned*>(&h1);
    packed.z = *reinterpret_cast<unsigned*>(&h2);
    packed.w = *reinterpret_cast<unsigned*>(&h3);
    reinterpret_cast<uint4*>(g_xh)[i] = packed;
}

// ---------------------------------------------------------------------------
struct AccH { __half2 h[4]; };   // 8 halves

__device__ __forceinline__ void hfma4(AccH& acc, __half2 w2, uint4 r) {
    acc.h[0] = __hfma2(w2, *reinterpret_cast<__half2*>(&r.x), acc.h[0]);
    acc.h[1] = __hfma2(w2, *reinterpret_cast<__half2*>(&r.y), acc.h[1]);
    acc.h[2] = __hfma2(w2, *reinterpret_cast<__half2*>(&r.z), acc.h[2]);
    acc.h[3] = __hfma2(w2, *reinterpret_cast<__half2*>(&r.w), acc.h[3]);
}

__device__ __forceinline__ void hadd4(AccH& acc, uint4 r) {
    acc.h[0] = __hadd2(acc.h[0], *reinterpret_cast<__half2*>(&r.x));
    acc.h[1] = __hadd2(acc.h[1], *reinterpret_cast<__half2*>(&r.y));
    acc.h[2] = __hadd2(acc.h[2], *reinterpret_cast<__half2*>(&r.z));
    acc.h[3] = __hadd2(acc.h[3], *reinterpret_cast<__half2*>(&r.w));
}

__device__ __forceinline__ void acc_to_f(const AccH& acc, float* f) {
    float2 a = __half22float2(acc.h[0]);
    float2 b = __half22float2(acc.h[1]);
    float2 c = __half22float2(acc.h[2]);
    float2 d = __half22float2(acc.h[3]);
    f[0] = a.x; f[1] = a.y; f[2] = b.x; f[3] = b.y;
    f[4] = c.x; f[5] = c.y; f[6] = d.x; f[7] = d.y;
}

// Layer 1: y1h[v] = fp16( dinv[v]^2 * sum dinv[u]*xh[u] ).  2 nodes/warp,
// 4-wide batches, HFMA2 accumulation, packed HMUL2 epilogue, ZROW padding.
__global__ void __launch_bounds__(256, 6) k_pull1(int N) {
    int w = (blockIdx.x * blockDim.x + threadIdx.x) >> 5;
    if (w * 2 >= N) return;
    int lane = threadIdx.x & 31;
    int v = min(w * 2 + (lane >> 4), N - 1);
    int sub = lane & 15;

    int n = __ldg(&g_cursor[v]);
    float dv = (n > 0) ? rsqrtf((float)n) : 0.0f;
    int dmax = __reduce_max_sync(0xffffffffu, n);
    const int* arow = &g_adj2[(size_t)v * ADJ_STRIDE];

    AccH acc = {};
    for (int j = 0; j < dmax; j += 4) {
        int4 ids = __ldg(reinterpret_cast<const int4*>(arow) + (j >> 2));
        int u0 = (j + 0 < n) ? ids.x : ZROW;
        int u1 = (j + 1 < n) ? ids.y : ZROW;
        int u2 = (j + 2 < n) ? ids.z : ZROW;
        int u3 = (j + 3 < n) ? ids.w : ZROW;
        __half w0 = __ldg(&g_dinvh[u0]);
        __half w1 = __ldg(&g_dinvh[u1]);
        __half w2 = __ldg(&g_dinvh[u2]);
        __half w3 = __ldg(&g_dinvh[u3]);
        uint4 a0 = __ldg(&reinterpret_cast<const uint4*>(g_xh + (size_t)u0 * DIMS)[sub]);
        uint4 a1 = __ldg(&reinterpret_cast<const uint4*>(g_xh + (size_t)u1 * DIMS)[sub]);
        uint4 a2 = __ldg(&reinterpret_cast<const uint4*>(g_xh + (size_t)u2 * DIMS)[sub]);
        uint4 a3 = __ldg(&reinterpret_cast<const uint4*>(g_xh + (size_t)u3 * DIMS)[sub]);
        hfma4(acc, __half2half2(w0), a0);
        hfma4(acc, __half2half2(w1), a1);
        hfma4(acc, __half2half2(w2), a2);
        hfma4(acc, __half2half2(w3), a3);
    }

    // y1 = dv^2 * acc, scaled in packed fp16 (values are small; y1 is stored
    // fp16 anyway so this adds no meaningful rounding).
    __half2 s2 = __float2half2_rn(dv * dv);
    uint4 packed;
    __half2 o0 = __hmul2(s2, acc.h[0]);
    __half2 o1 = __hmul2(s2, acc.h[1]);
    __half2 o2 = __hmul2(s2, acc.h[2]);
    __half2 o3 = __hmul2(s2, acc.h[3]);
    packed.x = *reinterpret_cast<unsigned*>(&o0);
    packed.y = *reinterpret_cast<unsigned*>(&o1);
    packed.z = *reinterpret_cast<unsigned*>(&o2);
    packed.w = *reinterpret_cast<unsigned*>(&o3);
    reinterpret_cast<uint4*>(&g_y1h[(size_t)v * DIMS])[sub] = packed;
}

__device__ __forceinline__ void unpack8(uint4 r, float* f) {
    float2 a = __half22float2(*reinterpret_cast<__half2*>(&r.x));
    float2 b = __half22float2(*reinterpret_cast<__half2*>(&r.y));
    float2 c = __half22float2(*reinterpret_cast<__half2*>(&r.z));
    float2 d = __half22float2(*reinterpret_cast<__half2*>(&r.w));
    f[0] = a.x; f[1] = a.y; f[2] = b.x; f[3] = b.y;
    f[4] = c.x; f[5] = c.y; f[6] = d.x; f[7] = d.y;
}

// Layer 2 + finalize. Inner loop: pure HADD2 sum of y1 rows.
// x2[v] = dinv[v] * sum_u y1[u];  x1[v] = y1[v]*sqrt(deg(v)).
// out[v] = (x0[v] + x1[v] + x2[v]) / 3.  Self rows prefetched before loop.
__global__ void __launch_bounds__(256, 6) k_pull2(float* __restrict__ out, int N) {
    int w = (blockIdx.x * blockDim.x + threadIdx.x) >> 5;
    if (w * 2 >= N) return;
    int lane = threadIdx.x & 31;
    int v = min(w * 2 + (lane >> 4), N - 1);
    int sub = lane & 15;

    int n = __ldg(&g_cursor[v]);
    float dv = (n > 0) ? rsqrtf((float)n) : 0.0f;
    float sq = (n > 0) ? sqrtf((float)n) : 0.0f;
    int dmax = __reduce_max_sync(0xffffffffu, n);
    const int* arow = &g_adj2[(size_t)v * ADJ_STRIDE];

    // Prefetch self rows; latency hides under the gather loop.
    uint4 x0r = __ldg(&reinterpret_cast<const uint4*>(g_xh  + (size_t)v * DIMS)[sub]);
    uint4 y1r = __ldg(&reinterpret_cast<const uint4*>(g_y1h + (size_t)v * DIMS)[sub]);

    AccH acc = {};
    for (int j = 0; j < dmax; j += 4) {
        int4 ids = __ldg(reinterpret_cast<const int4*>(arow) + (j >> 2));
        int u0 = (j + 0 < n) ? ids.x : ZROW;
        int u1 = (j + 1 < n) ? ids.y : ZROW;
        int u2 = (j + 2 < n) ? ids.z : ZROW;
        int u3 = (j + 3 < n) ? ids.w : ZROW;
        uint4 a0 = __ldg(&reinterpret_cast<const uint4*>(g_y1h + (size_t)u0 * DIMS)[sub]);
        uint4 a1 = __ldg(&reinterpret_cast<const uint4*>(g_y1h + (size_t)u1 * DIMS)[sub]);
        uint4 a2 = __ldg(&reinterpret_cast<const uint4*>(g_y1h + (size_t)u2 * DIMS)[sub]);
        uint4 a3 = __ldg(&reinterpret_cast<const uint4*>(g_y1h + (size_t)u3 * DIMS)[sub]);
        hadd4(acc, a0); hadd4(acc, a1);
        hadd4(acc, a2); hadd4(acc, a3);
    }

    float af[8], x0[8], y1[8];
    acc_to_f(acc, af);
    unpack8(x0r, x0);
    unpack8(y1r, y1);

    const float third = 1.0f / 3.0f;
    float4 oa, ob;
    oa.x = (x0[0] + y1[0] * sq + dv * af[0]) * third;
    oa.y = (x0[1] + y1[1] * sq + dv * af[1]) * third;
    oa.z = (x0[2] + y1[2] * sq + dv * af[2]) * third;
    oa.w = (x0[3] + y1[3] * sq + dv * af[3]) * third;
    ob.x = (x0[4] + y1[4] * sq + dv * af[4]) * third;
    ob.y = (x0[5] + y1[5] * sq + dv * af[5]) * third;
    ob.z = (x0[6] + y1[6] * sq + dv * af[6]) * third;
    ob.w = (x0[7] + y1[7] * sq + dv * af[7]) * third;
    float4* op = reinterpret_cast<float4*>(&out[(size_t)v * DIMS]);
    op[sub * 2]     = oa;
    op[sub * 2 + 1] = ob;
}

// ---------------------------------------------------------------------------
extern "C" void kernel_launch(void* const* d_in, const int* in_sizes, int n_in,
                              void* d_out, int out_size) {
    const float* user_emb = (const float*)d_in[0];
    const float* item_emb = (const float*)d_in[1];
    const int*   ui_src   = (const int*)d_in[2];
    const int*   ui_dst   = (const int*)d_in[3];
    // d_in[4..5] (iu_src/iu_dst) are the exact transpose; handled implicitly.

    const int U  = in_sizes[0] / DIMS;
    const int I  = in_sizes[1] / DIMS;
    const int E  = in_sizes[2];
    const int N  = U + I;
    const int UD = U * DIMS;
    const int ND8 = (N * DIMS) / 8;
    const int N4 = (N + 3) / 4;

    float* out = (float*)d_out;

    // One-time infra (created on the first, non-captured, correctness call).
    static cudaStream_t s_side = nullptr;
    static cudaEvent_t ev_fork = nullptr, ev_join = nullptr;
    if (s_side == nullptr) {
        cudaStreamCreateWithFlags(&s_side, cudaStreamNonBlocking);
        cudaEventCreateWithFlags(&ev_fork, cudaEventDisableTiming);
        cudaEventCreateWithFlags(&ev_join, cudaEventDisableTiming);
    }

    const int T = 256;
    int blks_n4 = (N4 + T - 1) / T;
    int blks_n  = (N + T - 1) / T;
    int blks_f  = (2 * E + T - 1) / T;
    int blks_c  = (ND8 + T - 1) / T;
    int warps   = (N + 1) / 2;                 // 2 nodes per warp
    int blks_pl = (warps * 32 + T - 1) / T;

    // Fork: convert (DRAM-bound) runs concurrently with the graph build.
    cudaEventRecord(ev_fork, 0);
    cudaStreamWaitEvent(s_side, ev_fork, 0);
    k_convert<<<blks_c, T, 0, s_side>>>(user_emb, item_emb, UD, ND8);
    cudaEventRecord(ev_join, s_side);

    // Build chain on the main stream.
    k_zero<<<blks_n4, T>>>(N4);
    k_fill<<<blks_f, T>>>(ui_src, ui_dst, E, U);
    k_meta<<<blks_n, T>>>(N);

    // Join: pull1 needs adjacency/dinvh tables and the fp16 feature table.
    cudaStreamWaitEvent(0, ev_join, 0);
    k_pull1<<<blks_pl, T>>>(N);
    k_pull2<<<blks_pl, T>>>(out, N);
}

// round 14
// speedup vs baseline: 1.3960x; 1.0559x over previous
#include <cuda_runtime.h>
#include <cuda_fp16.h>
#include <cstdint>

// LightGCN on GB300, round 14: R13 + 4 node-pairs per warp with parallel
// prologue prefetch (deg + first adj int4 for all 4 pairs issued before any
// processing) — collapses 4 serial L2 round-trip chains into 1, cuts CTA
// count 4x. U=100000, I=50000, D=128, E=300000.
#define DIMS 128
#define MAXN 160000
#define ZROW (MAXN - 1)        // never written; stays zero across replays
#define ADJ_STRIDE 64
#define NPAIR 4

__device__ int    g_cursor[MAXN];               // degree counter / fill cursor
__device__ __half g_dinvh[MAXN];                // rsqrt(deg) fp16; [ZROW]=0
__device__ int    g_adj2[(size_t)MAXN * ADJ_STRIDE];
__device__ __half g_xh[(size_t)MAXN * DIMS];    // fp16 x0    (row ZROW = 0)
__device__ __half g_y1h[(size_t)MAXN * DIMS];   // fp16 dinv[v]*x1[v] (ZROW = 0)

// ---------------------------------------------------------------------------
__global__ void k_zero(int N4) {
    int i = blockIdx.x * blockDim.x + threadIdx.x;
    if (i < N4) reinterpret_cast<int4*>(g_cursor)[i] = make_int4(0, 0, 0, 0);
}

// One endpoint insertion per thread (one atomic chain each).
__global__ void k_fill(const int* __restrict__ src, const int* __restrict__ dst,
                       int E, int U) {
    int t = blockIdx.x * blockDim.x + threadIdx.x;
    if (t >= 2 * E) return;
    int e = (t < E) ? t : t - E;
    int a = __ldg(&src[e]);
    int b = __ldg(&dst[e]) + U;
    int node = (t < E) ? b : a;
    int nbr  = (t < E) ? a : b;
    int p = atomicAdd(&g_cursor[node], 1);
    g_adj2[(size_t)node * ADJ_STRIDE + p] = nbr;
}

// dinvh table (deg stays in g_cursor; pulls rsqrt their own node).
__global__ void k_meta(int N) {
    int i = blockIdx.x * blockDim.x + threadIdx.x;
    if (i >= N) return;
    int d = g_cursor[i];
    float dinv = (d > 0) ? rsqrtf((float)d) : 0.0f;
    g_dinvh[i] = __float2half_rn(dinv);
}

// Convert concat(ue, ie) -> fp16 table; 8 floats per thread.
__global__ void k_convert(const float* __restrict__ ue, const float* __restrict__ ie,
                          int UD, int ND8) {
    int i = blockIdx.x * blockDim.x + threadIdx.x;
    if (i >= ND8) return;
    int base = i * 8;
    const float4* p = (base < UD)
        ? reinterpret_cast<const float4*>(ue + base)
        : reinterpret_cast<const float4*>(ie + (base - UD));
    float4 v0 = __ldg(p);
    float4 v1 = __ldg(p + 1);
    __half2 h0 = __floats2half2_rn(v0.x, v0.y);
    __half2 h1 = __floats2half2_rn(v0.z, v0.w);
    __half2 h2 = __floats2half2_rn(v1.x, v1.y);
    __half2 h3 = __floats2half2_rn(v1.z, v1.w);
    uint4 packed;
    packed.x = *reinterpret_cast<unsigned*>(&h0);
    packed.y = *reinterpret_cast<unsigned*>(&h1);
    packed.z = *reinterpret_cast<unsigned*>(&h2);
    packed.w = *reinterpret_cast<unsigned*>(&h3);
    reinterpret_cast<uint4*>(g_xh)[i] = packed;
}

// ---------------------------------------------------------------------------
struct AccH { __half2 h[4]; };   // 8 halves

__device__ __forceinline__ void hfma4(AccH& acc, __half2 w2, uint4 r) {
    acc.h[0] = __hfma2(w2, *reinterpret_cast<__half2*>(&r.x), acc.h[0]);
    acc.h[1] = __hfma2(w2, *reinterpret_cast<__half2*>(&r.y), acc.h[1]);
    acc.h[2] = __hfma2(w2, *reinterpret_cast<__half2*>(&r.z), acc.h[2]);
    acc.h[3] = __hfma2(w2, *reinterpret_cast<__half2*>(&r.w), acc.h[3]);
}

__device__ __forceinline__ void hadd4(AccH& acc, uint4 r) {
    acc.h[0] = __hadd2(acc.h[0], *reinterpret_cast<__half2*>(&r.x));
    acc.h[1] = __hadd2(acc.h[1], *reinterpret_cast<__half2*>(&r.y));
    acc.h[2] = __hadd2(acc.h[2], *reinterpret_cast<__half2*>(&r.z));
    acc.h[3] = __hadd2(acc.h[3], *reinterpret_cast<__half2*>(&r.w));
}

__device__ __forceinline__ void acc_to_f(const AccH& acc, float* f) {
    float2 a = __half22float2(acc.h[0]);
    float2 b = __half22float2(acc.h[1]);
    float2 c = __half22float2(acc.h[2]);
    float2 d = __half22float2(acc.h[3]);
    f[0] = a.x; f[1] = a.y; f[2] = b.x; f[3] = b.y;
    f[4] = c.x; f[5] = c.y; f[6] = d.x; f[7] = d.y;
}

__device__ __forceinline__ void unpack8(uint4 r, float* f) {
    float2 a = __half22float2(*reinterpret_cast<__half2*>(&r.x));
    float2 b = __half22float2(*reinterpret_cast<__half2*>(&r.y));
    float2 c = __half22float2(*reinterpret_cast<__half2*>(&r.z));
    float2 d = __half22float2(*reinterpret_cast<__half2*>(&r.w));
    f[0] = a.x; f[1] = a.y; f[2] = b.x; f[3] = b.y;
    f[4] = c.x; f[5] = c.y; f[6] = d.x; f[7] = d.y;
}

// Layer 1: y1h[v] = fp16( dinv[v]^2 * sum dinv[u]*xh[u] ).
// 4 strided node-pairs per warp; degrees and first adj int4 of all pairs
// prefetched before processing (parallel prologue).
__global__ void __launch_bounds__(128) k_pull1(int N, int WS) {
    int gw = (blockIdx.x * blockDim.x + threadIdx.x) >> 5;
    int lane = threadIdx.x & 31;
    int half = lane >> 4;
    int sub  = lane & 15;

    int  vv[NPAIR];
    int  nn[NPAIR];
    int4 id0[NPAIR];
    bool act[NPAIR];
    #pragma unroll
    for (int k = 0; k < NPAIR; k++) {
        int pr = gw + k * WS;                 // uniform per warp
        act[k] = (pr * 2 < N);
        int v = act[k] ? min(pr * 2 + half, N - 1) : half;
        vv[k] = v;
        nn[k] = __ldg(&g_cursor[v]);
        id0[k] = __ldg(reinterpret_cast<const int4*>(&g_adj2[(size_t)v * ADJ_STRIDE]));
    }

    #pragma unroll
    for (int k = 0; k < NPAIR; k++) {
        if (!act[k]) break;                   // uniform branch
        int v = vv[k];
        int n = nn[k];
        float dv = (n > 0) ? rsqrtf((float)n) : 0.0f;
        int dmax = __reduce_max_sync(0xffffffffu, n);
        const int* arow = &g_adj2[(size_t)v * ADJ_STRIDE];

        AccH acc = {};
        int4 ids = id0[k];
        for (int j = 0; j < dmax || j == 0; j += 4) {
            int u0 = (j + 0 < n) ? ids.x : ZROW;
            int u1 = (j + 1 < n) ? ids.y : ZROW;
            int u2 = (j + 2 < n) ? ids.z : ZROW;
            int u3 = (j + 3 < n) ? ids.w : ZROW;
            // prefetch next ids before gathers
            if (j + 4 < dmax)
                ids = __ldg(reinterpret_cast<const int4*>(arow) + ((j >> 2) + 1));
            __half w0 = __ldg(&g_dinvh[u0]);
            __half w1 = __ldg(&g_dinvh[u1]);
            __half w2 = __ldg(&g_dinvh[u2]);
            __half w3 = __ldg(&g_dinvh[u3]);
            uint4 a0 = __ldg(&reinterpret_cast<const uint4*>(g_xh + (size_t)u0 * DIMS)[sub]);
            uint4 a1 = __ldg(&reinterpret_cast<const uint4*>(g_xh + (size_t)u1 * DIMS)[sub]);
            uint4 a2 = __ldg(&reinterpret_cast<const uint4*>(g_xh + (size_t)u2 * DIMS)[sub]);
            uint4 a3 = __ldg(&reinterpret_cast<const uint4*>(g_xh + (size_t)u3 * DIMS)[sub]);
            hfma4(acc, __half2half2(w0), a0);
            hfma4(acc, __half2half2(w1), a1);
            hfma4(acc, __half2half2(w2), a2);
            hfma4(acc, __half2half2(w3), a3);
        }

        __half2 s2 = __float2half2_rn(dv * dv);
        uint4 packed;
        __half2 o0 = __hmul2(s2, acc.h[0]);
        __half2 o1 = __hmul2(s2, acc.h[1]);
        __half2 o2 = __hmul2(s2, acc.h[2]);
        __half2 o3 = __hmul2(s2, acc.h[3]);
        packed.x = *reinterpret_cast<unsigned*>(&o0);
        packed.y = *reinterpret_cast<unsigned*>(&o1);
        packed.z = *reinterpret_cast<unsigned*>(&o2);
        packed.w = *reinterpret_cast<unsigned*>(&o3);
        reinterpret_cast<uint4*>(&g_y1h[(size_t)v * DIMS])[sub] = packed;
    }
}

// Layer 2 + finalize: x2[v] = dinv[v]*sum y1[u];  x1[v] = y1[v]*sqrt(deg);
// out[v] = (x0[v] + x1[v] + x2[v]) / 3.  Same 4-pair batched prologue.
__global__ void __launch_bounds__(128) k_pull2(float* __restrict__ out, int N, int WS) {
    int gw = (blockIdx.x * blockDim.x + threadIdx.x) >> 5;
    int lane = threadIdx.x & 31;
    int half = lane >> 4;
    int sub  = lane & 15;

    int  vv[NPAIR];
    int  nn[NPAIR];
    int4 id0[NPAIR];
    bool act[NPAIR];
    #pragma unroll
    for (int k = 0; k < NPAIR; k++) {
        int pr = gw + k * WS;
        act[k] = (pr * 2 < N);
        int v = act[k] ? min(pr * 2 + half, N - 1) : half;
        vv[k] = v;
        nn[k] = __ldg(&g_cursor[v]);
        id0[k] = __ldg(reinterpret_cast<const int4*>(&g_adj2[(size_t)v * ADJ_STRIDE]));
    }

    #pragma unroll
    for (int k = 0; k < NPAIR; k++) {
        if (!act[k]) break;
        int v = vv[k];
        int n = nn[k];
        float dv = (n > 0) ? rsqrtf((float)n) : 0.0f;
        float sq = (n > 0) ? sqrtf((float)n) : 0.0f;
        int dmax = __reduce_max_sync(0xffffffffu, n);
        const int* arow = &g_adj2[(size_t)v * ADJ_STRIDE];

        // self rows: latency hides under the gather loop
        uint4 x0r = __ldg(&reinterpret_cast<const uint4*>(g_xh  + (size_t)v * DIMS)[sub]);
        uint4 y1r = __ldg(&reinterpret_cast<const uint4*>(g_y1h + (size_t)v * DIMS)[sub]);

        AccH acc = {};
        int4 ids = id0[k];
        for (int j = 0; j < dmax || j == 0; j += 4) {
            int u0 = (j + 0 < n) ? ids.x : ZROW;
            int u1 = (j + 1 < n) ? ids.y : ZROW;
            int u2 = (j + 2 < n) ? ids.z : ZROW;
            int u3 = (j + 3 < n) ? ids.w : ZROW;
            if (j + 4 < dmax)
                ids = __ldg(reinterpret_cast<const int4*>(arow) + ((j >> 2) + 1));
            uint4 a0 = __ldg(&reinterpret_cast<const uint4*>(g_y1h + (size_t)u0 * DIMS)[sub]);
            uint4 a1 = __ldg(&reinterpret_cast<const uint4*>(g_y1h + (size_t)u1 * DIMS)[sub]);
            uint4 a2 = __ldg(&reinterpret_cast<const uint4*>(g_y1h + (size_t)u2 * DIMS)[sub]);
            uint4 a3 = __ldg(&reinterpret_cast<const uint4*>(g_y1h + (size_t)u3 * DIMS)[sub]);
            hadd4(acc, a0); hadd4(acc, a1);
            hadd4(acc, a2); hadd4(acc, a3);
        }

        float af[8], x0[8], y1[8];
        acc_to_f(acc, af);
        unpack8(x0r, x0);
        unpack8(y1r, y1);

        const float third = 1.0f / 3.0f;
        float4 oa, ob;
        oa.x = (x0[0] + y1[0] * sq + dv * af[0]) * third;
        oa.y = (x0[1] + y1[1] * sq + dv * af[1]) * third;
        oa.z = (x0[2] + y1[2] * sq + dv * af[2]) * third;
        oa.w = (x0[3] + y1[3] * sq + dv * af[3]) * third;
        ob.x = (x0[4] + y1[4] * sq + dv * af[4]) * third;
        ob.y = (x0[5] + y1[5] * sq + dv * af[5]) * third;
        ob.z = (x0[6] + y1[6] * sq + dv * af[6]) * third;
        ob.w = (x0[7] + y1[7] * sq + dv * af[7]) * third;
        float4* op = reinterpret_cast<float4*>(&out[(size_t)v * DIMS]);
        op[sub * 2]     = oa;
        op[sub * 2 + 1] = ob;
    }
}

// ---------------------------------------------------------------------------
extern "C" void kernel_launch(void* const* d_in, const int* in_sizes, int n_in,
                              void* d_out, int out_size) {
    const float* user_emb = (const float*)d_in[0];
    const float* item_emb = (const float*)d_in[1];
    const int*   ui_src   = (const int*)d_in[2];
    const int*   ui_dst   = (const int*)d_in[3];
    // d_in[4..5] (iu_src/iu_dst) are the exact transpose; handled implicitly.

    const int U  = in_sizes[0] / DIMS;
    const int I  = in_sizes[1] / DIMS;
    const int E  = in_sizes[2];
    const int N  = U + I;
    const int UD = U * DIMS;
    const int ND8 = (N * DIMS) / 8;
    const int N4 = (N + 3) / 4;

    float* out = (float*)d_out;

    // One-time infra (created on the first, non-captured, correctness call).
    static cudaStream_t s_side = nullptr;
    static cudaEvent_t ev_fork = nullptr, ev_join = nullptr;
    if (s_side == nullptr) {
        cudaStreamCreateWithFlags(&s_side, cudaStreamNonBlocking);
        cudaEventCreateWithFlags(&ev_fork, cudaEventDisableTiming);
        cudaEventCreateWithFlags(&ev_join, cudaEventDisableTiming);
    }

    const int T = 256;
    int blks_n4 = (N4 + T - 1) / T;
    int blks_n  = (N + T - 1) / T;
    int blks_f  = (2 * E + T - 1) / T;
    int blks_c  = (ND8 + T - 1) / T;

    int pairs = (N + 1) / 2;                       // 2 nodes per pair
    int WS    = (pairs + NPAIR - 1) / NPAIR;       // warps needed (stride)
    const int TP = 128;
    int blks_pl = (WS * 32 + TP - 1) / TP;

    // Fork: convert (DRAM-bound) runs concurrently with the graph build.
    cudaEventRecord(ev_fork, 0);
    cudaStreamWaitEvent(s_side, ev_fork, 0);
    k_convert<<<blks_c, T, 0, s_side>>>(user_emb, item_emb, UD, ND8);
    cudaEventRecord(ev_join, s_side);

    // Build chain on the main stream.
    k_zero<<<blks_n4, T>>>(N4);
    k_fill<<<blks_f, T>>>(ui_src, ui_dst, E, U);
    k_meta<<<blks_n, T>>>(N);

    // Join: pull1 needs adjacency/dinvh tables and the fp16 feature table.
    cudaStreamWaitEvent(0, ev_join, 0);
    k_pull1<<<blks_pl, TP>>>(N, WS);
    k_pull2<<<blks_pl, TP>>>(out, N, WS);
}